// round 2
// baseline (speedup 1.0000x reference)
#include <cuda_runtime.h>

// LengthRegulator: out[b,t,:] = x[b,j,:] where frame t falls in token j's
// duration interval. Row duration sums are exactly T_OUT, so a scatter
// (each token writes its own frames) covers the output with no search.

#define BB 32
#define SS 512
#define DD 384
#define T_OUT 2048
#define DV (DD / 4)   // 96 float4 per row

// Scratch: exclusive-cumsum start offsets per (b, token). Device global to
// respect the no-allocation rule.
__device__ int g_start[BB * SS];

// Kernel 1: per-batch inclusive scan of durations -> exclusive starts.
// One block per batch, 512 threads, Hillis-Steele in shared memory.
__global__ void lr_scan_kernel(const int* __restrict__ dur) {
    __shared__ int s[SS];
    const int b = blockIdx.x;
    const int t = threadIdx.x;
    const int d = dur[b * SS + t];
    s[t] = d;
    __syncthreads();
    #pragma unroll
    for (int off = 1; off < SS; off <<= 1) {
        int v = (t >= off) ? s[t - off] : 0;
        __syncthreads();
        s[t] += v;
        __syncthreads();
    }
    // exclusive start = inclusive - own duration
    g_start[b * SS + t] = s[t] - d;
}

// Kernel 2: block (j, b) copies x[b,j,:] into out frames [start, start+dur).
// 96 threads, one float4 each: row read is one coalesced 1536B transaction,
// each frame write is one coalesced 1536B streaming-store transaction.
__global__ void lr_expand_kernel(const float4* __restrict__ x4,
                                 const int* __restrict__ dur,
                                 float4* __restrict__ out4) {
    const int j = blockIdx.x;
    const int b = blockIdx.y;
    const int c = threadIdx.x;           // 0..95
    const int idx = b * SS + j;

    const float4 v = __ldg(&x4[(size_t)idx * DV + c]);
    const int start = g_start[idx];
    const int d = dur[idx];

    float4* o = out4 + ((size_t)b * T_OUT + start) * DV + c;
    for (int k = 0; k < d; ++k) {
        __stcs(&o[(size_t)k * DV], v);   // streaming store: output never re-read
    }
}

extern "C" void kernel_launch(void* const* d_in, const int* in_sizes, int n_in,
                              void* d_out, int out_size) {
    const float4* x4  = (const float4*)d_in[0];       // x [B,S,D] f32
    const int*    dur = (const int*)d_in[1];          // durations [B,S] i32
    // d_in[2] = t_out scalar; fixed at T_OUT for this problem's shapes.
    float4* out4 = (float4*)d_out;                    // [B,T_OUT,D] f32

    lr_scan_kernel<<<BB, SS>>>(dur);
    lr_expand_kernel<<<dim3(SS, BB), DV>>>(x4, dur, out4);
}